// round 10
// baseline (speedup 1.0000x reference)
#include <cuda_runtime.h>
#include <math.h>

#define BB   4
#define SS   4096
#define QEPS 1e-6f

typedef unsigned long long u64;

// ---- scratch (no allocation allowed): K1 -> K2 hand-off ----
__device__ float g_rmx[BB * SS];
__device__ float g_rmy[BB * SS];
__device__ float g_k1x[BB * SS];
__device__ float g_k1y[BB * SS];
__device__ float g_inv[BB * SS];
__device__ float g_rowsum[BB * SS];

// ---- packed fp32x2 helpers (Blackwell FFMA2 pipe, PTX-only) ----
__device__ __forceinline__ u64 f2_mul(u64 a, u64 b) {
    u64 r; asm("mul.rn.f32x2 %0, %1, %2;" : "=l"(r) : "l"(a), "l"(b)); return r;
}
__device__ __forceinline__ u64 f2_fma(u64 a, u64 b, u64 c) {
    u64 r; asm("fma.rn.f32x2 %0, %1, %2, %3;" : "=l"(r) : "l"(a), "l"(b), "l"(c)); return r;
}
__device__ __forceinline__ u64 f2_add(u64 a, u64 b) {
    u64 r; asm("add.rn.f32x2 %0, %1, %2;" : "=l"(r) : "l"(a), "l"(b)); return r;
}
__device__ __forceinline__ u64 pack2(float lo, float hi) {
    u64 r; asm("mov.b64 %0, {%1, %2};" : "=l"(r) : "f"(lo), "f"(hi)); return r;
}
__device__ __forceinline__ void unpack2(u64 v, float& lo, float& hi) {
    asm("mov.b64 {%0, %1}, %2;" : "=f"(lo), "=f"(hi) : "l"(v));
}

__device__ __forceinline__ float warpSum(float v) {
    v += __shfl_xor_sync(0xffffffffu, v, 16);
    v += __shfl_xor_sync(0xffffffffu, v, 8);
    v += __shfl_xor_sync(0xffffffffu, v, 4);
    v += __shfl_xor_sync(0xffffffffu, v, 2);
    v += __shfl_xor_sync(0xffffffffu, v, 1);
    return v;
}

// Causal accumulate of (sum, sum*x, sum*y) for row pair (s0 < s1) over SoA smem.
// Phase A: t in [0, 2*(s0>>1)+1] feeds both rows (hi-half guard on row0 edge).
// Phase B: remaining t up to s1 feed row1 only. No dead predicated work.
__device__ __forceinline__ void accPair(
    const float* __restrict__ sx, const float* __restrict__ sy,
    int s0, int s1, int lane,
    float rs0x, float rs0y, float rs1x, float rs1y,
    float& A0, float& AX0, float& AY0,
    float& A1, float& AX1, float& AY1)
{
    const u64 rx0 = pack2(rs0x, rs0x), ry0 = pack2(rs0y, rs0y);
    const u64 rx1 = pack2(rs1x, rs1x), ry1 = pack2(rs1y, rs1y);
    u64 a0 = 0, ax0 = 0, ay0 = 0;
    u64 a1 = 0, ax1 = 0, ay1 = 0;

    const int iEndA = s0 >> 1;
    for (int i = lane; i <= iEndA; i += 32) {
        const u64 X = *(const u64*)(sx + 2 * i);   // {x_2i, x_2i+1}
        const u64 Y = *(const u64*)(sy + 2 * i);
        {   // row1: 2i+1 <= s0+1 <= s1 always in phase A
            u64 d = f2_fma(ry1, Y, f2_mul(rx1, X));
            float dl, dh; unpack2(d, dl, dh);
            dl = fmaxf(dl, 0.f); dh = fmaxf(dh, 0.f);
            u64 v = pack2(dl, dh);
            a1 = f2_add(a1, v); ax1 = f2_fma(v, X, ax1); ay1 = f2_fma(v, Y, ay1);
        }
        {   // row0: guard hi half at the causal edge
            u64 d = f2_fma(ry0, Y, f2_mul(rx0, X));
            float dl, dh; unpack2(d, dl, dh);
            dl = fmaxf(dl, 0.f);
            dh = (2 * i + 1 <= s0) ? fmaxf(dh, 0.f) : 0.f;
            u64 v = pack2(dl, dh);
            a0 = f2_add(a0, v); ax0 = f2_fma(v, X, ax0); ay0 = f2_fma(v, Y, ay0);
        }
    }
    const int iEndB = s1 >> 1;
    for (int i = iEndA + 1 + lane; i <= iEndB; i += 32) {
        const u64 X = *(const u64*)(sx + 2 * i);
        const u64 Y = *(const u64*)(sy + 2 * i);
        u64 d = f2_fma(ry1, Y, f2_mul(rx1, X));
        float dl, dh; unpack2(d, dl, dh);
        dl = fmaxf(dl, 0.f);
        dh = (2 * i + 1 <= s1) ? fmaxf(dh, 0.f) : 0.f;
        u64 v = pack2(dl, dh);
        a1 = f2_add(a1, v); ax1 = f2_fma(v, X, ax1); ay1 = f2_fma(v, Y, ay1);
    }

    float lo, hi;
    unpack2(a0,  lo, hi); A0  = warpSum(lo + hi);
    unpack2(ax0, lo, hi); AX0 = warpSum(lo + hi);
    unpack2(ay0, lo, hi); AY0 = warpSum(lo + hi);
    unpack2(a1,  lo, hi); A1  = warpSum(lo + hi);
    unpack2(ax1, lo, hi); AX1 = warpSum(lo + hi);
    unpack2(ay1, lo, hi); AY1 = warpSum(lo + hi);
}

// One full 4096-float score row from smem SoA, streaming float4 stores.
__device__ __forceinline__ void writeRowS(
    const float* __restrict__ sx, const float* __restrict__ sy,
    int s, float rx, float ry, float inv, float* __restrict__ out, int lane)
{
    const u64 RX = pack2(rx, rx), RY = pack2(ry, ry);
    for (int tb = lane * 4; tb < SS; tb += 128) {
        if (tb > s) {                                     // pure zero tail
            __stcs((float4*)(out + tb), make_float4(0.f, 0.f, 0.f, 0.f));
            continue;
        }
        const u64 Xa = *(const u64*)(sx + tb), Xb = *(const u64*)(sx + tb + 2);
        const u64 Ya = *(const u64*)(sy + tb), Yb = *(const u64*)(sy + tb + 2);
        u64 dA = f2_fma(RY, Ya, f2_mul(RX, Xa));
        u64 dB = f2_fma(RY, Yb, f2_mul(RX, Xb));
        float w0, w1, w2, w3;
        unpack2(dA, w0, w1); unpack2(dB, w2, w3);
        w0 = fmaxf(w0, 0.f) * inv;
        w1 = fmaxf(w1, 0.f) * inv;
        w2 = fmaxf(w2, 0.f) * inv;
        w3 = fmaxf(w3, 0.f) * inv;
        if (tb + 3 > s) {                                 // causal boundary
            if (tb + 1 > s) w1 = 0.f;
            if (tb + 2 > s) w2 = 0.f;
            if (tb + 3 > s) w3 = 0.f;
        }
        __stcs((float4*)(out + tb), make_float4(w0, w1, w2, w3));
    }
}

// Same, but reads r from global (L1-resident 32KB) — used by K2 whose smem holds r_mid.
__device__ __forceinline__ void writeRowG(
    const float4* __restrict__ rq,   // r batch base viewed as float4 (2 points each)
    int s, float rx, float ry, float inv, float* __restrict__ out, int lane)
{
    for (int tb = lane * 4; tb < SS; tb += 128) {
        if (tb > s) {
            __stcs((float4*)(out + tb), make_float4(0.f, 0.f, 0.f, 0.f));
            continue;
        }
        const float4 qa = __ldg(rq + (tb >> 1));
        const float4 qb = __ldg(rq + (tb >> 1) + 1);
        float w0 = fmaxf(fmaf(rx, qa.x, ry * qa.y), 0.f) * inv;
        float w1 = fmaxf(fmaf(rx, qa.z, ry * qa.w), 0.f) * inv;
        float w2 = fmaxf(fmaf(rx, qb.x, ry * qb.y), 0.f) * inv;
        float w3 = fmaxf(fmaf(rx, qb.z, ry * qb.w), 0.f) * inv;
        if (tb + 3 > s) {
            if (tb + 1 > s) w1 = 0.f;
            if (tb + 2 > s) w2 = 0.f;
            if (tb + 3 > s) w3 = 0.f;
        }
        __stcs((float4*)(out + tb), make_float4(w0, w1, w2, w3));
    }
}

// ---------------------------------------------------------------------------
// K1: pass-1 accumulate for all pairs; write HALF of this block's score rows
// (pairs with even local index). Stash rmid/k1/inv/rowsum for K2.
// ---------------------------------------------------------------------------
__global__ void __launch_bounds__(256)
qi_k1(const float* __restrict__ r, const float* __restrict__ dt,
      float* __restrict__ score)
{
    __shared__ __align__(16) float sx[SS];
    __shared__ __align__(16) float sy[SS];
    __shared__ float sInv[16];

    const int b     = blockIdx.y;
    const int tid   = threadIdx.x;
    const int warp  = tid >> 5, lane = tid & 31;
    const int bbase = blockIdx.x * 8;
    const float2* rb = (const float2*)r + (size_t)b * SS;
    const float dtb = dt[b];

    {   // SoA load of r (float4 = 2 points)
        const float4* rb4 = (const float4*)rb;
        for (int i = tid; i < SS / 2; i += 256) {
            float4 v = rb4[i];
            sx[2 * i] = v.x; sy[2 * i] = v.y;
            sx[2 * i + 1] = v.z; sy[2 * i + 1] = v.w;
        }
    }
    __syncthreads();

    const int s0 = bbase + warp, s1 = SS - 1 - s0;
    const float rs0x = sx[s0], rs0y = sy[s0];
    const float rs1x = sx[s1], rs1y = sy[s1];
    float A0, AX0, AY0, A1, AX1, AY1;
    accPair(sx, sy, s0, s1, lane, rs0x, rs0y, rs1x, rs1y,
            A0, AX0, AY0, A1, AX1, AY1);

    if (lane == 0) {
#pragma unroll
        for (int w = 0; w < 2; w++) {
            const int   s  = w ? s1 : s0;
            const float A  = w ? A1 : A0;
            const float AX = w ? AX1 : AX0;
            const float AY = w ? AY1 : AY0;
            const float rx = w ? rs1x : rs0x;
            const float ry = w ? rs1y : rs0y;
            const float inv = 1.0f / fmaxf(A, QEPS);
            float k1x = dtb * (AX * inv); if (!isfinite(k1x)) k1x = 0.f;
            float k1y = dtb * (AY * inv); if (!isfinite(k1y)) k1y = 0.f;
            float rmx = rx + k1x; if (!isfinite(rmx)) rmx = rx;
            float rmy = ry + k1y; if (!isfinite(rmy)) rmy = ry;
            const size_t idx = (size_t)b * SS + s;
            g_rmx[idx] = rmx;  g_rmy[idx] = rmy;
            g_k1x[idx] = k1x;  g_k1y[idx] = k1y;
            g_inv[idx] = inv;  g_rowsum[idx] = A * inv;
            sInv[2 * warp + w] = inv;
        }
    }
    __syncthreads();

    // Write rows of pairs with even local index i in {0,2,4,6}: 8 rows, 1/warp.
    const int i   = (warp >> 1) << 1;
    const int pp  = bbase + i;
    const int row = (warp & 1) ? (SS - 1 - pp) : pp;
    const float inv = sInv[2 * i + (warp & 1)];
    writeRowS(sx, sy, row, sx[row], sy[row], inv,
              score + ((size_t)b * SS + row) * SS, lane);
}

// ---------------------------------------------------------------------------
// K2: pass-2 accumulate on r_mid (smem) -> rfinal; write the OTHER HALF of the
// score rows (odd local pair index) from r via L1 — overlaps with the compute.
// ---------------------------------------------------------------------------
__global__ void __launch_bounds__(256)
qi_k2(const float* __restrict__ r, const float* __restrict__ dt,
      float* __restrict__ score, float* __restrict__ rfinal)
{
    __shared__ __align__(16) float mx[SS];
    __shared__ __align__(16) float my[SS];

    const int b     = blockIdx.y;
    const int tid   = threadIdx.x;
    const int warp  = tid >> 5, lane = tid & 31;
    const int bbase = blockIdx.x * 8;
    const float2* rb = (const float2*)r + (size_t)b * SS;
    const float dtb = dt[b];

    for (int i = tid; i < SS; i += 256) {
        mx[i] = g_rmx[(size_t)b * SS + i];
        my[i] = g_rmy[(size_t)b * SS + i];
    }
    __syncthreads();

    const int s0 = bbase + warp, s1 = SS - 1 - s0;
    const float m0x = mx[s0], m0y = my[s0];
    const float m1x = mx[s1], m1y = my[s1];
    float A0, AX0, AY0, A1, AX1, AY1;
    accPair(mx, my, s0, s1, lane, m0x, m0y, m1x, m1y,
            A0, AX0, AY0, A1, AX1, AY1);

    if (lane == 0) {
#pragma unroll
        for (int w = 0; w < 2; w++) {
            const int   s  = w ? s1 : s0;
            const float A  = w ? A1 : A0;
            const float AX = w ? AX1 : AX0;
            const float AY = w ? AY1 : AY0;
            const size_t idx = (size_t)b * SS + s;
            const float inv = 1.0f / fmaxf(A, QEPS);
            float k2x = dtb * (AX * inv); if (!isfinite(k2x)) k2x = 0.f;
            float k2y = dtb * (AY * inv); if (!isfinite(k2y)) k2y = 0.f;
            const float2 r0 = rb[s];
            float rnx = r0.x + 0.5f * (g_k1x[idx] + k2x);
            float rny = r0.y + 0.5f * (g_k1y[idx] + k2y);
            float nr  = fmaxf(sqrtf(rnx * rnx + rny * rny), QEPS);
            float ar  = fminf(fmaxf(nr + g_rowsum[idx] * 0.01f, 0.1f), 2.0f);
            float sc  = ar / nr;
            float fx = rnx * sc; if (!isfinite(fx)) fx = r0.x;
            float fy = rny * sc; if (!isfinite(fy)) fy = r0.y;
            ((float2*)rfinal)[idx] = make_float2(fx, fy);
        }
    }

    // Write rows of pairs with odd local index i in {1,3,5,7}.
    const int i   = ((warp >> 1) << 1) + 1;
    const int pp  = bbase + i;
    const int row = (warp & 1) ? (SS - 1 - pp) : pp;
    const float inv = g_inv[(size_t)b * SS + row];
    const float2 rr = __ldg(rb + row);
    writeRowG((const float4*)rb, row, rr.x, rr.y, inv,
              score + ((size_t)b * SS + row) * SS, lane);
}

extern "C" void kernel_launch(void* const* d_in, const int* in_sizes, int n_in,
                              void* d_out, int out_size) {
    const float* r  = (const float*)d_in[0];
    const float* dt = (const float*)d_in[1];
    if (in_sizes[0] == BB && in_sizes[1] == BB * SS * 2) {
        r  = (const float*)d_in[1];
        dt = (const float*)d_in[0];
    }
    float* out    = (float*)d_out;
    float* rfinal = out;                          // [B,S,2]
    float* score  = out + (size_t)BB * SS * 2;    // [B,S,S]

    dim3 grid(SS / 16, BB);                       // 256 blocks/batch, 8 pairs each
    qi_k1<<<grid, 256>>>(r, dt, score);
    qi_k2<<<grid, 256>>>(r, dt, score, rfinal);
}

// round 12
// speedup vs baseline: 1.0326x; 1.0326x over previous
#include <cuda_runtime.h>
#include <math.h>

#define BB   4
#define SS   4096
#define QEPS 1e-6f

typedef unsigned long long u64;

// ---- scratch (no allocation allowed): K1 -> K2 hand-off ----
__device__ float g_rmx[BB * SS];
__device__ float g_rmy[BB * SS];
__device__ float g_k1x[BB * SS];
__device__ float g_k1y[BB * SS];
__device__ float g_inv[BB * SS];
__device__ float g_rowsum[BB * SS];

// ---- packed fp32x2 helpers (Blackwell FFMA2 pipe, PTX-only) ----
__device__ __forceinline__ u64 f2_mul(u64 a, u64 b) {
    u64 r; asm("mul.rn.f32x2 %0, %1, %2;" : "=l"(r) : "l"(a), "l"(b)); return r;
}
__device__ __forceinline__ u64 f2_fma(u64 a, u64 b, u64 c) {
    u64 r; asm("fma.rn.f32x2 %0, %1, %2, %3;" : "=l"(r) : "l"(a), "l"(b), "l"(c)); return r;
}
__device__ __forceinline__ u64 f2_add(u64 a, u64 b) {
    u64 r; asm("add.rn.f32x2 %0, %1, %2;" : "=l"(r) : "l"(a), "l"(b)); return r;
}
__device__ __forceinline__ u64 pack2(float lo, float hi) {
    u64 r; asm("mov.b64 %0, {%1, %2};" : "=l"(r) : "f"(lo), "f"(hi)); return r;
}
__device__ __forceinline__ void unpack2(u64 v, float& lo, float& hi) {
    asm("mov.b64 {%0, %1}, %2;" : "=f"(lo), "=f"(hi) : "l"(v));
}

__device__ __forceinline__ float warpSum(float v) {
    v += __shfl_xor_sync(0xffffffffu, v, 16);
    v += __shfl_xor_sync(0xffffffffu, v, 8);
    v += __shfl_xor_sync(0xffffffffu, v, 4);
    v += __shfl_xor_sync(0xffffffffu, v, 2);
    v += __shfl_xor_sync(0xffffffffu, v, 1);
    return v;
}

// Causal accumulate of (sum, sum*x, sum*y) for row pair (s0 < s1) over SoA smem.
// Phase A feeds both rows; phase B feeds row1 only. No dead predicated work.
__device__ __forceinline__ void accPair(
    const float* __restrict__ sx, const float* __restrict__ sy,
    int s0, int s1, int lane,
    float rs0x, float rs0y, float rs1x, float rs1y,
    float& A0, float& AX0, float& AY0,
    float& A1, float& AX1, float& AY1)
{
    const u64 rx0 = pack2(rs0x, rs0x), ry0 = pack2(rs0y, rs0y);
    const u64 rx1 = pack2(rs1x, rs1x), ry1 = pack2(rs1y, rs1y);
    u64 a0 = 0, ax0 = 0, ay0 = 0;
    u64 a1 = 0, ax1 = 0, ay1 = 0;

    const int iEndA = s0 >> 1;
    for (int i = lane; i <= iEndA; i += 32) {
        const u64 X = *(const u64*)(sx + 2 * i);
        const u64 Y = *(const u64*)(sy + 2 * i);
        {   // row1: always fully causal in phase A
            u64 d = f2_fma(ry1, Y, f2_mul(rx1, X));
            float dl, dh; unpack2(d, dl, dh);
            dl = fmaxf(dl, 0.f); dh = fmaxf(dh, 0.f);
            u64 v = pack2(dl, dh);
            a1 = f2_add(a1, v); ax1 = f2_fma(v, X, ax1); ay1 = f2_fma(v, Y, ay1);
        }
        {   // row0: guard hi half at the causal edge
            u64 d = f2_fma(ry0, Y, f2_mul(rx0, X));
            float dl, dh; unpack2(d, dl, dh);
            dl = fmaxf(dl, 0.f);
            dh = (2 * i + 1 <= s0) ? fmaxf(dh, 0.f) : 0.f;
            u64 v = pack2(dl, dh);
            a0 = f2_add(a0, v); ax0 = f2_fma(v, X, ax0); ay0 = f2_fma(v, Y, ay0);
        }
    }
    const int iEndB = s1 >> 1;
    for (int i = iEndA + 1 + lane; i <= iEndB; i += 32) {
        const u64 X = *(const u64*)(sx + 2 * i);
        const u64 Y = *(const u64*)(sy + 2 * i);
        u64 d = f2_fma(ry1, Y, f2_mul(rx1, X));
        float dl, dh; unpack2(d, dl, dh);
        dl = fmaxf(dl, 0.f);
        dh = (2 * i + 1 <= s1) ? fmaxf(dh, 0.f) : 0.f;
        u64 v = pack2(dl, dh);
        a1 = f2_add(a1, v); ax1 = f2_fma(v, X, ax1); ay1 = f2_fma(v, Y, ay1);
    }

    float lo, hi;
    unpack2(a0,  lo, hi); A0  = warpSum(lo + hi);
    unpack2(ax0, lo, hi); AX0 = warpSum(lo + hi);
    unpack2(ay0, lo, hi); AY0 = warpSum(lo + hi);
    unpack2(a1,  lo, hi); A1  = warpSum(lo + hi);
    unpack2(ax1, lo, hi); AX1 = warpSum(lo + hi);
    unpack2(ay1, lo, hi); AY1 = warpSum(lo + hi);
}

// One full 4096-float score row from smem SoA, streaming float4 stores.
__device__ __forceinline__ void writeRowS(
    const float* __restrict__ sx, const float* __restrict__ sy,
    int s, float rx, float ry, float inv, float* __restrict__ out, int lane)
{
    const u64 RX = pack2(rx, rx), RY = pack2(ry, ry);
    for (int tb = lane * 4; tb < SS; tb += 128) {
        if (tb > s) {                                     // pure zero tail
            __stcs((float4*)(out + tb), make_float4(0.f, 0.f, 0.f, 0.f));
            continue;
        }
        const u64 Xa = *(const u64*)(sx + tb), Xb = *(const u64*)(sx + tb + 2);
        const u64 Ya = *(const u64*)(sy + tb), Yb = *(const u64*)(sy + tb + 2);
        u64 dA = f2_fma(RY, Ya, f2_mul(RX, Xa));
        u64 dB = f2_fma(RY, Yb, f2_mul(RX, Xb));
        float w0, w1, w2, w3;
        unpack2(dA, w0, w1); unpack2(dB, w2, w3);
        w0 = fmaxf(w0, 0.f) * inv;
        w1 = fmaxf(w1, 0.f) * inv;
        w2 = fmaxf(w2, 0.f) * inv;
        w3 = fmaxf(w3, 0.f) * inv;
        if (tb + 3 > s) {                                 // causal boundary
            if (tb + 1 > s) w1 = 0.f;
            if (tb + 2 > s) w2 = 0.f;
            if (tb + 3 > s) w3 = 0.f;
        }
        __stcs((float4*)(out + tb), make_float4(w0, w1, w2, w3));
    }
}

// ---------------------------------------------------------------------------
// K1: pass-1 accumulate ONLY (no score writes). 128 blocks/batch, 2 pairs/warp.
// ---------------------------------------------------------------------------
__global__ void __launch_bounds__(256)
qi_k1(const float* __restrict__ r, const float* __restrict__ dt)
{
    __shared__ __align__(16) float sx[SS];
    __shared__ __align__(16) float sy[SS];

    const int b    = blockIdx.y;
    const int tid  = threadIdx.x;
    const int warp = tid >> 5, lane = tid & 31;
    const float2* rb = (const float2*)r + (size_t)b * SS;
    const float dtb = dt[b];

    {   // SoA load of r (float4 = 2 points)
        const float4* rb4 = (const float4*)rb;
        for (int i = tid; i < SS / 2; i += 256) {
            float4 v = rb4[i];
            sx[2 * i] = v.x;     sy[2 * i] = v.y;
            sx[2 * i + 1] = v.z; sy[2 * i + 1] = v.w;
        }
    }
    __syncthreads();

#pragma unroll
    for (int rep = 0; rep < 2; rep++) {
        const int p  = blockIdx.x * 16 + rep * 8 + warp;   // [0, 2048)
        const int s0 = p, s1 = SS - 1 - p;
        const float rs0x = sx[s0], rs0y = sy[s0];
        const float rs1x = sx[s1], rs1y = sy[s1];
        float A0, AX0, AY0, A1, AX1, AY1;
        accPair(sx, sy, s0, s1, lane, rs0x, rs0y, rs1x, rs1y,
                A0, AX0, AY0, A1, AX1, AY1);
        if (lane == 0) {
#pragma unroll
            for (int w = 0; w < 2; w++) {
                const int   s  = w ? s1 : s0;
                const float A  = w ? A1 : A0;
                const float AX = w ? AX1 : AX0;
                const float AY = w ? AY1 : AY0;
                const float rx = w ? rs1x : rs0x;
                const float ry = w ? rs1y : rs0y;
                const float inv = 1.0f / fmaxf(A, QEPS);
                float k1x = dtb * (AX * inv); if (!isfinite(k1x)) k1x = 0.f;
                float k1y = dtb * (AY * inv); if (!isfinite(k1y)) k1y = 0.f;
                float rmx = rx + k1x; if (!isfinite(rmx)) rmx = rx;
                float rmy = ry + k1y; if (!isfinite(rmy)) rmy = ry;
                const size_t idx = (size_t)b * SS + s;
                g_rmx[idx] = rmx;  g_rmy[idx] = rmy;
                g_k1x[idx] = k1x;  g_k1y[idx] = k1y;
                g_inv[idx] = inv;  g_rowsum[idx] = A * inv;
            }
        }
    }
}

// ---------------------------------------------------------------------------
// K2: role-split, NO inter-block sync (all deps come from K1 via global).
//   blockIdx.x % 3 == 2  -> compute role: pass-2 accumulate on r_mid + rfinal
//   else                 -> writer role: stream score rows from r in smem
// Per batch: 192 blocks = 128 writers + 64 compute, interleaved so every SM
// hosts both roles; DRAM stays saturated while pass-2 compute hides under it.
// The role branch is uniform per block, so all __syncthreads are uniform.
// ---------------------------------------------------------------------------
__global__ void __launch_bounds__(256)
qi_k2(const float* __restrict__ r, const float* __restrict__ dt,
      float* __restrict__ score, float* __restrict__ rfinal)
{
    __shared__ __align__(16) float sx[SS];
    __shared__ __align__(16) float sy[SS];

    const int b    = blockIdx.y;
    const int bx   = blockIdx.x;
    const int tid  = threadIdx.x;
    const int warp = tid >> 5, lane = tid & 31;
    const float2* rb = (const float2*)r + (size_t)b * SS;
    float* scoreb = score + (size_t)b * SS * SS;

    if (bx % 3 == 2) {
        // ================= compute role =================
        const float dtb = dt[b];
        for (int i = tid; i < SS; i += 256) {
            sx[i] = g_rmx[(size_t)b * SS + i];
            sy[i] = g_rmy[(size_t)b * SS + i];
        }
        __syncthreads();

        const int c = bx / 3;                      // [0, 64)
        const int u = c * 8 + warp;                // [0, 512)
#pragma unroll
        for (int k = 0; k < 4; k++) {
            const int p  = u * 4 + k;              // [0, 2048)
            const int s0 = p, s1 = SS - 1 - p;
            const float m0x = sx[s0], m0y = sy[s0];
            const float m1x = sx[s1], m1y = sy[s1];
            float A0, AX0, AY0, A1, AX1, AY1;
            accPair(sx, sy, s0, s1, lane, m0x, m0y, m1x, m1y,
                    A0, AX0, AY0, A1, AX1, AY1);
            if (lane == 0) {
#pragma unroll
                for (int w = 0; w < 2; w++) {
                    const int   s  = w ? s1 : s0;
                    const float A  = w ? A1 : A0;
                    const float AX = w ? AX1 : AX0;
                    const float AY = w ? AY1 : AY0;
                    const size_t idx = (size_t)b * SS + s;
                    const float inv = 1.0f / fmaxf(A, QEPS);
                    float k2x = dtb * (AX * inv); if (!isfinite(k2x)) k2x = 0.f;
                    float k2y = dtb * (AY * inv); if (!isfinite(k2y)) k2y = 0.f;
                    const float2 r0 = rb[s];
                    float rnx = r0.x + 0.5f * (g_k1x[idx] + k2x);
                    float rny = r0.y + 0.5f * (g_k1y[idx] + k2y);
                    float nr  = fmaxf(sqrtf(rnx * rnx + rny * rny), QEPS);
                    float ar  = fminf(fmaxf(nr + g_rowsum[idx] * 0.01f, 0.1f), 2.0f);
                    float sc  = ar / nr;
                    float fx = rnx * sc; if (!isfinite(fx)) fx = r0.x;
                    float fy = rny * sc; if (!isfinite(fy)) fy = r0.y;
                    ((float2*)rfinal)[idx] = make_float2(fx, fy);
                }
            }
        }
    } else {
        // ================= writer role =================
        {   // SoA load of r
            const float4* rb4 = (const float4*)rb;
            for (int i = tid; i < SS / 2; i += 256) {
                float4 v = rb4[i];
                sx[2 * i] = v.x;     sy[2 * i] = v.y;
                sx[2 * i + 1] = v.z; sy[2 * i + 1] = v.w;
            }
        }
        __syncthreads();

        const int w = (bx / 3) * 2 + (bx % 3);     // [0, 128)
        const int u = w * 8 + warp;                // [0, 1024)
        // 4 rows per warp: {u, 4095-u, u+1024, 3071-u} — partitions [0,4096),
        // byte-balanced (every row stores a full 16 KB including zero tail).
        int rows[4];
        rows[0] = u;
        rows[1] = SS - 1 - u;
        rows[2] = u + 1024;
        rows[3] = SS - 1 - (u + 1024);
#pragma unroll
        for (int k = 0; k < 4; k++) {
            const int s = rows[k];
            const float inv = g_inv[(size_t)b * SS + s];
            writeRowS(sx, sy, s, sx[s], sy[s], inv,
                      scoreb + (size_t)s * SS, lane);
        }
    }
}

extern "C" void kernel_launch(void* const* d_in, const int* in_sizes, int n_in,
                              void* d_out, int out_size) {
    const float* r  = (const float*)d_in[0];
    const float* dt = (const float*)d_in[1];
    if (in_sizes[0] == BB && in_sizes[1] == BB * SS * 2) {
        r  = (const float*)d_in[1];
        dt = (const float*)d_in[0];
    }
    float* out    = (float*)d_out;
    float* rfinal = out;                          // [B,S,2]
    float* score  = out + (size_t)BB * SS * 2;    // [B,S,S]

    qi_k1<<<dim3(128, BB), 256>>>(r, dt);                  // pass-1 accumulate
    qi_k2<<<dim3(192, BB), 256>>>(r, dt, score, rfinal);   // writes + pass-2
}